// round 1
// baseline (speedup 1.0000x reference)
#include <cuda_runtime.h>
#include <math.h>

#define DD    768
#define NB    4
#define TT    4096
#define NROWS (NB*TT)   // 16384

// ---------------- scratch (static device globals; no runtime allocation) ----
__device__ float g_y1[NROWS*DD];
__device__ float g_q [NROWS*DD];
__device__ float g_k [NROWS*DD];
__device__ float g_v [NROWS*DD];
__device__ float g_ao[NROWS*DD];
__device__ float g_y2[NROWS*DD];
__device__ float g_h [NROWS*DD];
__device__ float g_s [(size_t)NB*TT*TT];   // 4*4096*4096 fp32 = 268 MB

// ---------------- LayerNorm (faithful to buggy reference) -------------------
// y = (x - mean/sqrt(var)) * g + b,  var unbiased (ddof=1)
__global__ __launch_bounds__(256)
void ln_kernel(const float* __restrict__ x, const float* __restrict__ g,
               const float* __restrict__ b, float* __restrict__ y)
{
    const int row = blockIdx.x;
    const float* xr = x + (long)row * DD;
    float* yr = y + (long)row * DD;
    const int tid = threadIdx.x;

    float v0 = xr[tid], v1 = xr[tid + 256], v2 = xr[tid + 512];
    float s  = v0 + v1 + v2;
    float ss = v0*v0 + v1*v1 + v2*v2;

    __shared__ float rs[8], rss[8];
    #pragma unroll
    for (int o = 16; o; o >>= 1) {
        s  += __shfl_xor_sync(0xffffffffu, s,  o);
        ss += __shfl_xor_sync(0xffffffffu, ss, o);
    }
    if ((tid & 31) == 0) { rs[tid >> 5] = s; rss[tid >> 5] = ss; }
    __syncthreads();
    float ts = 0.f, tss = 0.f;
    #pragma unroll
    for (int i = 0; i < 8; i++) { ts += rs[i]; tss += rss[i]; }

    const float mean  = ts * (1.0f / DD);
    const float var   = (tss - ts * ts * (1.0f / DD)) * (1.0f / (DD - 1));
    const float shift = mean * rsqrtf(var);   // mu / sqrt(var)  (the "bug")

    yr[tid]       = (v0 - shift) * g[tid]       + b[tid];
    yr[tid + 256] = (v1 - shift) * g[tid + 256] + b[tid + 256];
    yr[tid + 512] = (v2 - shift) * g[tid + 512] + b[tid + 512];
}

// ---------------- Row softmax over T=4096 with scale ------------------------
__global__ __launch_bounds__(256)
void softmax_kernel(float* __restrict__ S)
{
    const size_t row = blockIdx.x;
    float4* p = (float4*)(S + row * (size_t)TT);
    const int tid = threadIdx.x;
    const float scale = 0.03608439182435161f;   // 1/sqrt(768)

    float4 r[4];
    float mx = -3.0e38f;
    #pragma unroll
    for (int i = 0; i < 4; i++) {
        float4 t = p[tid + i * 256];
        t.x *= scale; t.y *= scale; t.z *= scale; t.w *= scale;
        r[i] = t;
        mx = fmaxf(mx, fmaxf(fmaxf(t.x, t.y), fmaxf(t.z, t.w)));
    }

    __shared__ float red[8];
    #pragma unroll
    for (int o = 16; o; o >>= 1) mx = fmaxf(mx, __shfl_xor_sync(0xffffffffu, mx, o));
    if ((tid & 31) == 0) red[tid >> 5] = mx;
    __syncthreads();
    #pragma unroll
    for (int i = 0; i < 8; i++) mx = fmaxf(mx, red[i]);

    float sum = 0.f;
    #pragma unroll
    for (int i = 0; i < 4; i++) {
        r[i].x = __expf(r[i].x - mx); r[i].y = __expf(r[i].y - mx);
        r[i].z = __expf(r[i].z - mx); r[i].w = __expf(r[i].w - mx);
        sum += r[i].x + r[i].y + r[i].z + r[i].w;
    }
    __syncthreads();   // before reusing red[]
    #pragma unroll
    for (int o = 16; o; o >>= 1) sum += __shfl_xor_sync(0xffffffffu, sum, o);
    if ((tid & 31) == 0) red[tid >> 5] = sum;
    __syncthreads();
    float tot = 0.f;
    #pragma unroll
    for (int i = 0; i < 8; i++) tot += red[i];
    const float inv = 1.0f / tot;

    #pragma unroll
    for (int i = 0; i < 4; i++) {
        r[i].x *= inv; r[i].y *= inv; r[i].z *= inv; r[i].w *= inv;
        p[tid + i * 256] = r[i];
    }
}

// ---------------- Tiled SGEMM: C = A * op(B) [+ epilogue] -------------------
// A: [M,K] row-major. If TB: B is [N,K] row-major (C=A*B^T), else B is [K,N].
// EPI: 0 = plain store, 1 = relu(C + bias[n]), 2 = C + bias[n] + resid[m,n].
// All of M,N divisible by 128; K divisible by 16. blockIdx.z = batch.
template <bool TB, int EPI>
__global__ __launch_bounds__(256)
void gemm_kernel(const float* __restrict__ A, const float* __restrict__ Bm,
                 float* __restrict__ C, int M, int N, int K,
                 long sA, long sB, long sC,
                 const float* __restrict__ bias, const float* __restrict__ resid)
{
    const int bz = blockIdx.z;
    A  += (long)bz * sA;
    Bm += (long)bz * sB;
    C  += (long)bz * sC;

    __shared__ float As[16][128];
    __shared__ float Bs[16][128];

    const int tid  = threadIdx.x;
    const int row0 = blockIdx.y * 128;
    const int col0 = blockIdx.x * 128;
    const int tm   = (tid / 16) * 8;
    const int tn   = (tid % 16) * 8;

    // loader indices (128x16 tile as 512 float4, 2 per thread)
    const int ar = tid / 4;
    const int ac = (tid % 4) * 4;
    // loader for [16,128] tile (non-transposed B)
    const int br = tid / 32;
    const int bc = (tid % 32) * 4;

    float acc[8][8] = {};

    for (int k0 = 0; k0 < K; k0 += 16) {
        #pragma unroll
        for (int it = 0; it < 2; it++) {
            const int i = ar + it * 64;
            const float4 va = *(const float4*)(A + (long)(row0 + i) * K + k0 + ac);
            As[ac + 0][i] = va.x; As[ac + 1][i] = va.y;
            As[ac + 2][i] = va.z; As[ac + 3][i] = va.w;
        }
        if (TB) {
            #pragma unroll
            for (int it = 0; it < 2; it++) {
                const int i = ar + it * 64;
                const float4 vb = *(const float4*)(Bm + (long)(col0 + i) * K + k0 + ac);
                Bs[ac + 0][i] = vb.x; Bs[ac + 1][i] = vb.y;
                Bs[ac + 2][i] = vb.z; Bs[ac + 3][i] = vb.w;
            }
        } else {
            #pragma unroll
            for (int it = 0; it < 2; it++) {
                const int j = br + it * 8;
                *(float4*)(&Bs[j][bc]) =
                    *(const float4*)(Bm + (long)(k0 + j) * N + col0 + bc);
            }
        }
        __syncthreads();

        #pragma unroll
        for (int kk = 0; kk < 16; kk++) {
            float a[8], bb[8];
            *(float4*)(a)      = *(float4*)(&As[kk][tm]);
            *(float4*)(a + 4)  = *(float4*)(&As[kk][tm + 4]);
            *(float4*)(bb)     = *(float4*)(&Bs[kk][tn]);
            *(float4*)(bb + 4) = *(float4*)(&Bs[kk][tn + 4]);
            #pragma unroll
            for (int i = 0; i < 8; i++)
                #pragma unroll
                for (int j = 0; j < 8; j++)
                    acc[i][j] += a[i] * bb[j];
        }
        __syncthreads();
    }

    #pragma unroll
    for (int i = 0; i < 8; i++) {
        const int gm = row0 + tm + i;
        #pragma unroll
        for (int j = 0; j < 8; j += 4) {
            const int gn = col0 + tn + j;
            float4 c = make_float4(acc[i][j], acc[i][j+1], acc[i][j+2], acc[i][j+3]);
            if (EPI == 1) {
                c.x = fmaxf(c.x + bias[gn+0], 0.f);
                c.y = fmaxf(c.y + bias[gn+1], 0.f);
                c.z = fmaxf(c.z + bias[gn+2], 0.f);
                c.w = fmaxf(c.w + bias[gn+3], 0.f);
            } else if (EPI == 2) {
                const float4 r = *(const float4*)(resid + (long)gm * N + gn);
                c.x += bias[gn+0] + r.x;
                c.y += bias[gn+1] + r.y;
                c.z += bias[gn+2] + r.z;
                c.w += bias[gn+3] + r.w;
            }
            *(float4*)(C + (long)gm * N + gn) = c;
        }
    }
}

// ---------------- launch ----------------------------------------------------
extern "C" void kernel_launch(void* const* d_in, const int* in_sizes, int n_in,
                              void* d_out, int out_size)
{
    (void)in_sizes; (void)n_in; (void)out_size;
    const float* x     = (const float*)d_in[0];
    const float* ln1_g = (const float*)d_in[1];
    const float* ln1_b = (const float*)d_in[2];
    const float* wq    = (const float*)d_in[3];
    const float* wk    = (const float*)d_in[4];
    const float* wv    = (const float*)d_in[5];
    const float* ln2_g = (const float*)d_in[6];
    const float* ln2_b = (const float*)d_in[7];
    const float* fc1w  = (const float*)d_in[8];
    const float* fc1b  = (const float*)d_in[9];
    const float* fc2w  = (const float*)d_in[10];
    const float* fc2b  = (const float*)d_in[11];
    float* out = (float*)d_out;

    float *y1, *q, *k, *v, *s, *ao, *y2, *h;
    cudaGetSymbolAddress((void**)&y1, g_y1);
    cudaGetSymbolAddress((void**)&q,  g_q);
    cudaGetSymbolAddress((void**)&k,  g_k);
    cudaGetSymbolAddress((void**)&v,  g_v);
    cudaGetSymbolAddress((void**)&s,  g_s);
    cudaGetSymbolAddress((void**)&ao, g_ao);
    cudaGetSymbolAddress((void**)&y2, g_y2);
    cudaGetSymbolAddress((void**)&h,  g_h);

    // 1. LN1
    ln_kernel<<<NROWS, 256>>>(x, ln1_g, ln1_b, y1);

    // 2. Q,K,V projections: [16384,768] @ [768,768] (NN)
    dim3 gqkv(DD / 128, NROWS / 128, 1);
    gemm_kernel<false, 0><<<gqkv, 256>>>(y1, wq, q, NROWS, DD, DD, 0, 0, 0, nullptr, nullptr);
    gemm_kernel<false, 0><<<gqkv, 256>>>(y1, wk, k, NROWS, DD, DD, 0, 0, 0, nullptr, nullptr);
    gemm_kernel<false, 0><<<gqkv, 256>>>(y1, wv, v, NROWS, DD, DD, 0, 0, 0, nullptr, nullptr);

    // 3. S = Q @ K^T per batch (NT), batched over z
    dim3 gs(TT / 128, TT / 128, NB);
    gemm_kernel<true, 0><<<gs, 256>>>(q, k, s, TT, TT, DD,
                                      (long)TT * DD, (long)TT * DD, (long)TT * TT,
                                      nullptr, nullptr);

    // 4. row softmax with 1/sqrt(D) scale
    softmax_kernel<<<NROWS, 256>>>(s);

    // 5. O = P @ V per batch (NN)
    dim3 gpv(DD / 128, TT / 128, NB);
    gemm_kernel<false, 0><<<gpv, 256>>>(s, v, ao, TT, DD, TT,
                                        (long)TT * TT, (long)TT * DD, (long)TT * DD,
                                        nullptr, nullptr);

    // 6. LN2
    ln_kernel<<<NROWS, 256>>>(ao, ln2_g, ln2_b, y2);

    // 7. MLP fc1: relu(y2 @ fc1w^T + fc1b)   (NT, torch Linear layout)
    gemm_kernel<true, 1><<<gqkv, 256>>>(y2, fc1w, h, NROWS, DD, DD, 0, 0, 0, fc1b, nullptr);

    // 8. MLP fc2 + residual: out = x + (h @ fc2w^T + fc2b)
    gemm_kernel<true, 2><<<gqkv, 256>>>(h, fc2w, out, NROWS, DD, DD, 0, 0, 0, fc2b, x);
}

// round 10
// speedup vs baseline: 5.4760x; 5.4760x over previous
#include <cuda_runtime.h>
#include <cuda_fp16.h>
#include <cstdint>
#include <math.h>

#define DD    768
#define NB    4
#define TT    4096
#define NROWS (NB*TT)   // 16384

// ---------------- scratch (static device globals) ---------------------------
__device__ __half g_y1[NROWS*DD];
__device__ __half g_q [NROWS*DD];
__device__ __half g_k [NROWS*DD];
__device__ __half g_v [NROWS*DD];
__device__ __half g_vt[NROWS*DD];
__device__ __half g_y2[NROWS*DD];
__device__ __half g_h [NROWS*DD];
__device__ __half g_wt[3*DD*DD];           // wq^T, wk^T, wv^T (fp16)
__device__ __half g_fw[2*DD*DD];           // fc1_w, fc2_w (fp16, already [N][K])
__device__ float  g_ao[NROWS*DD];
__device__ float  g_s [(size_t)NB*TT*TT];  // 268 MB attention logits (fp32)
__device__ __half g_p [(size_t)NB*TT*TT];  // 134 MB attention probs (fp16)

// ---------------- helpers ----------------------------------------------------
__device__ __forceinline__ uint32_t s2u(const void* p) {
    uint32_t a;
    asm("{ .reg .u64 t; cvta.to.shared.u64 t, %1; cvt.u32.u64 %0, t; }" : "=r"(a) : "l"(p));
    return a;
}
__device__ __forceinline__ void cpa16(uint32_t s, const void* g) {
    asm volatile("cp.async.cg.shared.global [%0], [%1], 16;" :: "r"(s), "l"(g));
}
__device__ __forceinline__ void ldm4(uint32_t* r, uint32_t a) {
    asm volatile("ldmatrix.sync.aligned.m8n8.x4.shared.b16 {%0,%1,%2,%3}, [%4];"
                 : "=r"(r[0]), "=r"(r[1]), "=r"(r[2]), "=r"(r[3]) : "r"(a));
}
__device__ __forceinline__ void mma16816(float* c, const uint32_t* a, uint32_t b0, uint32_t b1) {
    asm volatile("mma.sync.aligned.m16n8k16.row.col.f32.f16.f16.f32 "
                 "{%0,%1,%2,%3},{%4,%5,%6,%7},{%8,%9},{%0,%1,%2,%3};"
                 : "+f"(c[0]), "+f"(c[1]), "+f"(c[2]), "+f"(c[3])
                 : "r"(a[0]), "r"(a[1]), "r"(a[2]), "r"(a[3]), "r"(b0), "r"(b1));
}
__device__ __forceinline__ void st2(float* p, float a, float b)  { *(float2*)p = make_float2(a, b); }
__device__ __forceinline__ void st2(__half* p, float a, float b) { *(__half2*)p = __floats2half2_rn(a, b); }
__device__ __forceinline__ float tofl(float v)  { return v; }
__device__ __forceinline__ float tofl(__half v) { return __half2float(v); }

// ---------------- fp16 mma.sync GEMM -----------------------------------------
// C[M,N] = A[M,K] * B[N,K]^T, A/B fp16 K-major, fp32 accumulate; batch = grid.z
// EPI: 0 plain, 1 relu(c+bias[n]), 2 c+bias[n]+resid[m][n]
#define BM 128
#define BN 256
#define BKH 32                      // halfs per k-chunk
#define PITCH 40                    // halfs per smem row (80 B, conflict-free)
#define ATILE (BM*PITCH*2)          // 10240 B
#define BTILE (BN*PITCH*2)          // 20480 B
#define STAGEB (ATILE+BTILE)
#define NSTAGE 3
#define SMEMB (NSTAGE*STAGEB)       // 92160 B

__device__ __forceinline__ void load_stage(
    uint32_t smb, int st, int t, const __half* A, const __half* B,
    int lda, int ldb, int m0, int n0, int rr, int chunk)
{
    const uint32_t base = smb + (uint32_t)st * STAGEB;
    const long kb = (long)t * BKH + chunk * 8;
    #pragma unroll
    for (int it = 0; it < 2; it++) {
        const int row = rr + it * 64;
        cpa16(base + (uint32_t)row * 80u + (uint32_t)chunk * 16u,
              A + (long)(m0 + row) * lda + kb);
    }
    const uint32_t bb = base + ATILE;
    #pragma unroll
    for (int it = 0; it < 4; it++) {
        const int row = rr + it * 64;
        cpa16(bb + (uint32_t)row * 80u + (uint32_t)chunk * 16u,
              B + (long)(n0 + row) * ldb + kb);
    }
}

template <int EPI, typename OutT>
__global__ __launch_bounds__(256, 1)
void gemm_h(const __half* __restrict__ A, const __half* __restrict__ B,
            OutT* __restrict__ C, int lda, int ldb, int ldc, int K,
            long sA, long sB, long sC,
            const float* __restrict__ bias, const float* __restrict__ resid)
{
    extern __shared__ char sm[];
    const uint32_t smb = s2u(sm);
    const int tid = threadIdx.x;
    const int m0 = blockIdx.y * BM;
    const int n0 = blockIdx.x * BN;
    A += (long)blockIdx.z * sA;
    B += (long)blockIdx.z * sB;
    C += (long)blockIdx.z * sC;

    const int rr = tid >> 2, chunk = tid & 3;
    const int lane = tid & 31, warp = tid >> 5;
    const int wm = warp & 1, wn = warp >> 1;          // 2 x 4 warp grid
    const int r16 = lane & 15, cf = lane >> 4;

    const int nch = K / BKH;

    load_stage(smb, 0, 0, A, B, lda, ldb, m0, n0, rr, chunk);
    asm volatile("cp.async.commit_group;" ::: "memory");
    load_stage(smb, 1, 1, A, B, lda, ldb, m0, n0, rr, chunk);
    asm volatile("cp.async.commit_group;" ::: "memory");

    float acc[4][8][4];
    #pragma unroll
    for (int i = 0; i < 4; i++)
        #pragma unroll
        for (int j = 0; j < 8; j++)
            #pragma unroll
            for (int v = 0; v < 4; v++) acc[i][j][v] = 0.f;

    for (int t = 0; t < nch; t++) {
        asm volatile("cp.async.wait_group 1;" ::: "memory");
        __syncthreads();
        if (t + 2 < nch)
            load_stage(smb, (t + 2) % NSTAGE, t + 2, A, B, lda, ldb, m0, n0, rr, chunk);
        asm volatile("cp.async.commit_group;" ::: "memory");

        const uint32_t sA0 = smb + (uint32_t)(t % NSTAGE) * STAGEB;
        const uint32_t sB0 = sA0 + ATILE;
        #pragma unroll
        for (int ks = 0; ks < 2; ks++) {
            uint32_t a[4][4], b[4][4];
            #pragma unroll
            for (int mt = 0; mt < 4; mt++)
                ldm4(a[mt], sA0 + (uint32_t)(wm * 64 + mt * 16 + r16) * 80u
                              + (uint32_t)(ks * 16 + cf * 8) * 2u);
            #pragma unroll
            for (int np = 0; np < 4; np++)
                ldm4(b[np], sB0 + (uint32_t)(wn * 64 + np * 16 + r16) * 80u
                              + (uint32_t)(ks * 16 + cf * 8) * 2u);
            #pragma unroll
            for (int mt = 0; mt < 4; mt++)
                #pragma unroll
                for (int nt = 0; nt < 8; nt++) {
                    const int np = nt >> 1, sel = nt & 1;
                    mma16816(acc[mt][nt], a[mt], b[np][sel], b[np][sel + 2]);
                }
        }
    }

    // ---- epilogue ----
    const int q4 = lane >> 2, r4 = (lane & 3) * 2;
    #pragma unroll
    for (int mt = 0; mt < 4; mt++) {
        const int gm0 = m0 + wm * 64 + mt * 16 + q4;
        #pragma unroll
        for (int nt = 0; nt < 8; nt++) {
            const int gn = n0 + wn * 64 + nt * 8 + r4;
            float b0 = 0.f, b1 = 0.f;
            if (EPI != 0) { b0 = bias[gn]; b1 = bias[gn + 1]; }
            #pragma unroll
            for (int h = 0; h < 2; h++) {
                const int gm = gm0 + h * 8;
                float x0 = acc[mt][nt][h * 2], x1 = acc[mt][nt][h * 2 + 1];
                if (EPI == 1) {
                    x0 = fmaxf(x0 + b0, 0.f);
                    x1 = fmaxf(x1 + b1, 0.f);
                } else if (EPI == 2) {
                    const float2 rv = *(const float2*)(resid + (long)gm * ldc + gn);
                    x0 += b0 + rv.x;
                    x1 += b1 + rv.y;
                }
                st2(C + (long)gm * ldc + gn, x0, x1);
            }
        }
    }
}

// ---------------- LayerNorm (buggy-faithful), fp16 output -------------------
__global__ __launch_bounds__(256)
void ln_kernel(const float* __restrict__ x, const float* __restrict__ g,
               const float* __restrict__ b, __half* __restrict__ y)
{
    const int row = blockIdx.x;
    const float* xr = x + (long)row * DD;
    __half* yr = y + (long)row * DD;
    const int tid = threadIdx.x;

    float v0 = xr[tid], v1 = xr[tid + 256], v2 = xr[tid + 512];
    float s  = v0 + v1 + v2;
    float ss = v0*v0 + v1*v1 + v2*v2;

    __shared__ float rs[8], rss[8];
    #pragma unroll
    for (int o = 16; o; o >>= 1) {
        s  += __shfl_xor_sync(0xffffffffu, s,  o);
        ss += __shfl_xor_sync(0xffffffffu, ss, o);
    }
    if ((tid & 31) == 0) { rs[tid >> 5] = s; rss[tid >> 5] = ss; }
    __syncthreads();
    float ts = 0.f, tss = 0.f;
    #pragma unroll
    for (int i = 0; i < 8; i++) { ts += rs[i]; tss += rss[i]; }

    const float mean  = ts * (1.0f / DD);
    const float var   = (tss - ts * ts * (1.0f / DD)) * (1.0f / (DD - 1));
    const float shift = mean * rsqrtf(var);   // mu / sqrt(var)  (the "bug")

    yr[tid]       = __float2half((v0 - shift) * g[tid]       + b[tid]);
    yr[tid + 256] = __float2half((v1 - shift) * g[tid + 256] + b[tid + 256]);
    yr[tid + 512] = __float2half((v2 - shift) * g[tid + 512] + b[tid + 512]);
}

// ---------------- Row softmax: fp32 logits -> fp16 probs --------------------
__global__ __launch_bounds__(256)
void softmax_kernel(const float* __restrict__ S, __half* __restrict__ P)
{
    const size_t row = blockIdx.x;
    const float4* p = (const float4*)(S + row * (size_t)TT);
    __half2* o = (__half2*)(P + row * (size_t)TT);
    const int tid = threadIdx.x;
    const float scale = 0.03608439182435161f;   // 1/sqrt(768)

    float4 r[4];
    float mx = -3.0e38f;
    #pragma unroll
    for (int i = 0; i < 4; i++) {
        float4 t = p[tid + i * 256];
        t.x *= scale; t.y *= scale; t.z *= scale; t.w *= scale;
        r[i] = t;
        mx = fmaxf(mx, fmaxf(fmaxf(t.x, t.y), fmaxf(t.z, t.w)));
    }
    __shared__ float red[8];
    #pragma unroll
    for (int o2 = 16; o2; o2 >>= 1) mx = fmaxf(mx, __shfl_xor_sync(0xffffffffu, mx, o2));
    if ((tid & 31) == 0) red[tid >> 5] = mx;
    __syncthreads();
    #pragma unroll
    for (int i = 0; i < 8; i++) mx = fmaxf(mx, red[i]);

    float sum = 0.f;
    #pragma unroll
    for (int i = 0; i < 4; i++) {
        r[i].x = __expf(r[i].x - mx); r[i].y = __expf(r[i].y - mx);
        r[i].z = __expf(r[i].z - mx); r[i].w = __expf(r[i].w - mx);
        sum += r[i].x + r[i].y + r[i].z + r[i].w;
    }
    __syncthreads();
    #pragma unroll
    for (int o2 = 16; o2; o2 >>= 1) sum += __shfl_xor_sync(0xffffffffu, sum, o2);
    if ((tid & 31) == 0) red[tid >> 5] = sum;
    __syncthreads();
    float tot = 0.f;
    #pragma unroll
    for (int i = 0; i < 8; i++) tot += red[i];
    const float inv = 1.0f / tot;

    #pragma unroll
    for (int i = 0; i < 4; i++) {
        const int j = tid + i * 256;
        o[j * 2]     = __floats2half2_rn(r[i].x * inv, r[i].y * inv);
        o[j * 2 + 1] = __floats2half2_rn(r[i].z * inv, r[i].w * inv);
    }
}

// ---------------- transpose -> fp16: out[c][r] = in[r][c] -------------------
template <typename TIn>
__global__ __launch_bounds__(256)
void transpose_h(const TIn* __restrict__ in, __half* __restrict__ out,
                 int rows, int cols, long sIn, long sOut)
{
    __shared__ float tle[32][33];
    in  += (long)blockIdx.z * sIn;
    out += (long)blockIdx.z * sOut;
    const int c0 = blockIdx.x * 32, r0 = blockIdx.y * 32;
    const int tx = threadIdx.x & 31, ty = threadIdx.x >> 5;   // 32x8
    #pragma unroll
    for (int i = 0; i < 32; i += 8)
        tle[ty + i][tx] = tofl(in[(long)(r0 + ty + i) * cols + c0 + tx]);
    __syncthreads();
    #pragma unroll
    for (int i = 0; i < 32; i += 8)
        out[(long)(c0 + ty + i) * rows + r0 + tx] = __float2half(tle[tx][ty + i]);
}

// ---------------- fp32 -> fp16 copy (fc weights) ----------------------------
__global__ __launch_bounds__(256)
void cvt_h(const float* __restrict__ in, __half* __restrict__ out, int n4)
{
    const int i = blockIdx.x * 256 + threadIdx.x;
    if (i < n4) {
        const float4 v = ((const float4*)in)[i];
        __half2* o = (__half2*)out;
        o[i * 2]     = __floats2half2_rn(v.x, v.y);
        o[i * 2 + 1] = __floats2half2_rn(v.z, v.w);
    }
}

// ---------------- launch ----------------------------------------------------
extern "C" void kernel_launch(void* const* d_in, const int* in_sizes, int n_in,
                              void* d_out, int out_size)
{
    (void)in_sizes; (void)n_in; (void)out_size;
    const float* x     = (const float*)d_in[0];
    const float* ln1_g = (const float*)d_in[1];
    const float* ln1_b = (const float*)d_in[2];
    const float* wq    = (const float*)d_in[3];
    const float* wk    = (const float*)d_in[4];
    const float* wv    = (const float*)d_in[5];
    const float* ln2_g = (const float*)d_in[6];
    const float* ln2_b = (const float*)d_in[7];
    const float* fc1w  = (const float*)d_in[8];
    const float* fc1b  = (const float*)d_in[9];
    const float* fc2w  = (const float*)d_in[10];
    const float* fc2b  = (const float*)d_in[11];
    float* out = (float*)d_out;

    __half *y1, *q, *k, *v, *vt, *y2, *h, *wt, *fw, *p;
    float *s, *ao;
    cudaGetSymbolAddress((void**)&y1, g_y1);
    cudaGetSymbolAddress((void**)&q,  g_q);
    cudaGetSymbolAddress((void**)&k,  g_k);
    cudaGetSymbolAddress((void**)&v,  g_v);
    cudaGetSymbolAddress((void**)&vt, g_vt);
    cudaGetSymbolAddress((void**)&y2, g_y2);
    cudaGetSymbolAddress((void**)&h,  g_h);
    cudaGetSymbolAddress((void**)&wt, g_wt);
    cudaGetSymbolAddress((void**)&fw, g_fw);
    cudaGetSymbolAddress((void**)&p,  g_p);
    cudaGetSymbolAddress((void**)&s,  g_s);
    cudaGetSymbolAddress((void**)&ao, g_ao);

    cudaFuncSetAttribute(gemm_h<0, __half>, cudaFuncAttributeMaxDynamicSharedMemorySize, SMEMB);
    cudaFuncSetAttribute(gemm_h<0, float>,  cudaFuncAttributeMaxDynamicSharedMemorySize, SMEMB);
    cudaFuncSetAttribute(gemm_h<1, __half>, cudaFuncAttributeMaxDynamicSharedMemorySize, SMEMB);
    cudaFuncSetAttribute(gemm_h<2, float>,  cudaFuncAttributeMaxDynamicSharedMemorySize, SMEMB);

    // 1. LN1 -> fp16
    ln_kernel<<<NROWS, 256>>>(x, ln1_g, ln1_b, y1);

    // 2. weight prep: transpose wq/wk/wv -> fp16 [out][in]; convert fc weights
    dim3 gw(DD / 32, DD / 32, 1);
    transpose_h<float><<<gw, 256>>>(wq, wt + 0 * DD * DD, DD, DD, 0, 0);
    transpose_h<float><<<gw, 256>>>(wk, wt + 1 * DD * DD, DD, DD, 0, 0);
    transpose_h<float><<<gw, 256>>>(wv, wt + 2 * DD * DD, DD, DD, 0, 0);
    cvt_h<<<(DD * DD / 4 + 255) / 256, 256>>>(fc1w, fw + 0 * DD * DD, DD * DD / 4);
    cvt_h<<<(DD * DD / 4 + 255) / 256, 256>>>(fc2w, fw + 1 * DD * DD, DD * DD / 4);

    // 3. Q, K, V projections: [16384,768] x [768,768]^T -> fp16
    dim3 gproj(DD / BN, NROWS / BM, 1);
    gemm_h<0, __half><<<gproj, 256, SMEMB>>>(y1, wt + 0 * DD * DD, q, DD, DD, DD, DD, 0, 0, 0, nullptr, nullptr);
    gemm_h<0, __half><<<gproj, 256, SMEMB>>>(y1, wt + 1 * DD * DD, k, DD, DD, DD, DD, 0, 0, 0, nullptr, nullptr);
    gemm_h<0, __half><<<gproj, 256, SMEMB>>>(y1, wt + 2 * DD * DD, v, DD, DD, DD, DD, 0, 0, 0, nullptr, nullptr);

    // 4. S = Q K^T per batch -> fp32 logits
    dim3 gs(TT / BN, TT / BM, NB);
    gemm_h<0, float><<<gs, 256, SMEMB>>>(q, k, s, DD, DD, TT, DD,
                                         (long)TT * DD, (long)TT * DD, (long)TT * TT, nullptr, nullptr);

    // 5. softmax -> fp16 probs
    softmax_kernel<<<NROWS, 256>>>(s, p);

    // 6. V^T per batch: [4096,768] -> [768,4096] fp16
    dim3 gvt(DD / 32, TT / 32, NB);
    transpose_h<__half><<<gvt, 256>>>(v, vt, TT, DD, (long)TT * DD, (long)DD * TT);

    // 7. O = P V per batch -> fp32
    dim3 gpv(DD / BN, TT / BM, NB);
    gemm_h<0, float><<<gpv, 256, SMEMB>>>(p, vt, ao, TT, TT, DD, TT,
                                          (long)TT * TT, (long)DD * TT, (long)TT * DD, nullptr, nullptr);

    // 8. LN2 -> fp16
    ln_kernel<<<NROWS, 256>>>(ao, ln2_g, ln2_b, y2);

    // 9. fc1: relu(y2 fc1w^T + b) -> fp16
    gemm_h<1, __half><<<gproj, 256, SMEMB>>>(y2, fw + 0 * DD * DD, h, DD, DD, DD, DD, 0, 0, 0, fc1b, nullptr);

    // 10. fc2 + bias + residual -> out (fp32)
    gemm_h<2, float><<<gproj, 256, SMEMB>>>(h, fw + 1 * DD * DD, out, DD, DD, DD, DD, 0, 0, 0, fc2b, x);
}

// round 11
// speedup vs baseline: 5.6041x; 1.0234x over previous
#include <cuda_runtime.h>
#include <cuda_fp16.h>
#include <cstdint>
#include <math.h>

#define DD    768
#define NB    4
#define TT    4096
#define NROWS (NB*TT)   // 16384

// ---------------- scratch (static device globals) ---------------------------
__device__ __half g_y1[NROWS*DD];
__device__ __half g_qkv[3*NROWS*DD];       // q | k | v contiguous (batched GEMM out)
__device__ __half g_vt[NROWS*DD];
__device__ __half g_y2[NROWS*DD];
__device__ __half g_h [NROWS*DD];
__device__ __half g_wt[3*DD*DD];           // wq^T, wk^T, wv^T (fp16)
__device__ __half g_fw[2*DD*DD];           // fc1_w, fc2_w (fp16, already [N][K])
__device__ float  g_ao[NROWS*DD];
__device__ float  g_s [(size_t)NB*TT*TT];  // 268 MB attention logits (fp32)
__device__ __half g_p [(size_t)NB*TT*TT];  // 134 MB attention probs (fp16)

// ---------------- helpers ----------------------------------------------------
__device__ __forceinline__ uint32_t s2u(const void* p) {
    uint32_t a;
    asm("{ .reg .u64 t; cvta.to.shared.u64 t, %1; cvt.u32.u64 %0, t; }" : "=r"(a) : "l"(p));
    return a;
}
__device__ __forceinline__ void cpa16(uint32_t s, const void* g) {
    asm volatile("cp.async.cg.shared.global [%0], [%1], 16;" :: "r"(s), "l"(g));
}
__device__ __forceinline__ void ldm4(uint32_t* r, uint32_t a) {
    asm volatile("ldmatrix.sync.aligned.m8n8.x4.shared.b16 {%0,%1,%2,%3}, [%4];"
                 : "=r"(r[0]), "=r"(r[1]), "=r"(r[2]), "=r"(r[3]) : "r"(a));
}
__device__ __forceinline__ void mma16816(float* c, const uint32_t* a, uint32_t b0, uint32_t b1) {
    asm volatile("mma.sync.aligned.m16n8k16.row.col.f32.f16.f16.f32 "
                 "{%0,%1,%2,%3},{%4,%5,%6,%7},{%8,%9},{%0,%1,%2,%3};"
                 : "+f"(c[0]), "+f"(c[1]), "+f"(c[2]), "+f"(c[3])
                 : "r"(a[0]), "r"(a[1]), "r"(a[2]), "r"(a[3]), "r"(b0), "r"(b1));
}
__device__ __forceinline__ void st2(float* p, float a, float b)  { *(float2*)p = make_float2(a, b); }
__device__ __forceinline__ void st2(__half* p, float a, float b) { *(__half2*)p = __floats2half2_rn(a, b); }
__device__ __forceinline__ float tofl(float v)  { return v; }
__device__ __forceinline__ float tofl(__half v) { return __half2float(v); }

// ---------------- fp16 mma.sync GEMM -----------------------------------------
// C[M,N] = A[M,K] * B[N,K]^T, A/B fp16 K-major, fp32 accumulate; batch = grid.z
// EPI: 0 plain, 1 relu(c+bias[n]), 2 c+bias[n]+resid[m][n]
#define BM 128
#define BN 256
#define BKH 32                      // halfs per k-chunk
#define PITCH 40                    // halfs per smem row (80 B, conflict-free)
#define ATILE (BM*PITCH*2)          // 10240 B
#define BTILE (BN*PITCH*2)          // 20480 B
#define STAGEB (ATILE+BTILE)
#define NSTAGE 3
#define SMEMB (NSTAGE*STAGEB)       // 92160 B

__device__ __forceinline__ void load_stage(
    uint32_t smb, int st, int t, const __half* A, const __half* B,
    int lda, int ldb, int m0, int n0, int rr, int chunk)
{
    const uint32_t base = smb + (uint32_t)st * STAGEB;
    const long kb = (long)t * BKH + chunk * 8;
    #pragma unroll
    for (int it = 0; it < 2; it++) {
        const int row = rr + it * 64;
        cpa16(base + (uint32_t)row * 80u + (uint32_t)chunk * 16u,
              A + (long)(m0 + row) * lda + kb);
    }
    const uint32_t bb = base + ATILE;
    #pragma unroll
    for (int it = 0; it < 4; it++) {
        const int row = rr + it * 64;
        cpa16(bb + (uint32_t)row * 80u + (uint32_t)chunk * 16u,
              B + (long)(n0 + row) * ldb + kb);
    }
}

template <int EPI, typename OutT>
__global__ __launch_bounds__(256, 1)
void gemm_h(const __half* __restrict__ A, const __half* __restrict__ B,
            OutT* __restrict__ C, int lda, int ldb, int ldc, int K,
            long sA, long sB, long sC,
            const float* __restrict__ bias, const float* __restrict__ resid)
{
    extern __shared__ char sm[];
    const uint32_t smb = s2u(sm);
    const int tid = threadIdx.x;
    const int m0 = blockIdx.y * BM;
    const int n0 = blockIdx.x * BN;
    A += (long)blockIdx.z * sA;
    B += (long)blockIdx.z * sB;
    C += (long)blockIdx.z * sC;

    const int rr = tid >> 2, chunk = tid & 3;
    const int lane = tid & 31, warp = tid >> 5;
    const int wm = warp & 1, wn = warp >> 1;          // 2 x 4 warp grid
    const int r16 = lane & 15, cf = lane >> 4;

    const int nch = K / BKH;

    load_stage(smb, 0, 0, A, B, lda, ldb, m0, n0, rr, chunk);
    asm volatile("cp.async.commit_group;" ::: "memory");
    load_stage(smb, 1, 1, A, B, lda, ldb, m0, n0, rr, chunk);
    asm volatile("cp.async.commit_group;" ::: "memory");

    float acc[4][8][4];
    #pragma unroll
    for (int i = 0; i < 4; i++)
        #pragma unroll
        for (int j = 0; j < 8; j++)
            #pragma unroll
            for (int v = 0; v < 4; v++) acc[i][j][v] = 0.f;

    for (int t = 0; t < nch; t++) {
        asm volatile("cp.async.wait_group 1;" ::: "memory");
        __syncthreads();
        if (t + 2 < nch)
            load_stage(smb, (t + 2) % NSTAGE, t + 2, A, B, lda, ldb, m0, n0, rr, chunk);
        asm volatile("cp.async.commit_group;" ::: "memory");

        const uint32_t sA0 = smb + (uint32_t)(t % NSTAGE) * STAGEB;
        const uint32_t sB0 = sA0 + ATILE;
        #pragma unroll
        for (int ks = 0; ks < 2; ks++) {
            uint32_t a[4][4], b[4][4];
            #pragma unroll
            for (int mt = 0; mt < 4; mt++)
                ldm4(a[mt], sA0 + (uint32_t)(wm * 64 + mt * 16 + r16) * 80u
                              + (uint32_t)(ks * 16 + cf * 8) * 2u);
            #pragma unroll
            for (int np = 0; np < 4; np++)
                ldm4(b[np], sB0 + (uint32_t)(wn * 64 + np * 16 + r16) * 80u
                              + (uint32_t)(ks * 16 + cf * 8) * 2u);
            #pragma unroll
            for (int mt = 0; mt < 4; mt++)
                #pragma unroll
                for (int nt = 0; nt < 8; nt++) {
                    const int np = nt >> 1, sel = nt & 1;
                    mma16816(acc[mt][nt], a[mt], b[np][sel], b[np][sel + 2]);
                }
        }
    }

    // ---- epilogue ----
    const int q4 = lane >> 2, r4 = (lane & 3) * 2;
    #pragma unroll
    for (int mt = 0; mt < 4; mt++) {
        const int gm0 = m0 + wm * 64 + mt * 16 + q4;
        #pragma unroll
        for (int nt = 0; nt < 8; nt++) {
            const int gn = n0 + wn * 64 + nt * 8 + r4;
            float b0 = 0.f, b1 = 0.f;
            if (EPI != 0) { b0 = bias[gn]; b1 = bias[gn + 1]; }
            #pragma unroll
            for (int h = 0; h < 2; h++) {
                const int gm = gm0 + h * 8;
                float x0 = acc[mt][nt][h * 2], x1 = acc[mt][nt][h * 2 + 1];
                if (EPI == 1) {
                    x0 = fmaxf(x0 + b0, 0.f);
                    x1 = fmaxf(x1 + b1, 0.f);
                } else if (EPI == 2) {
                    const float2 rv = *(const float2*)(resid + (long)gm * ldc + gn);
                    x0 += b0 + rv.x;
                    x1 += b1 + rv.y;
                }
                st2(C + (long)gm * ldc + gn, x0, x1);
            }
        }
    }
}

// ---------------- LayerNorm (buggy-faithful), fp16 output -------------------
__global__ __launch_bounds__(256)
void ln_kernel(const float* __restrict__ x, const float* __restrict__ g,
               const float* __restrict__ b, __half* __restrict__ y)
{
    const int row = blockIdx.x;
    const float* xr = x + (long)row * DD;
    __half* yr = y + (long)row * DD;
    const int tid = threadIdx.x;

    float v0 = xr[tid], v1 = xr[tid + 256], v2 = xr[tid + 512];
    float s  = v0 + v1 + v2;
    float ss = v0*v0 + v1*v1 + v2*v2;

    __shared__ float rs[8], rss[8];
    #pragma unroll
    for (int o = 16; o; o >>= 1) {
        s  += __shfl_xor_sync(0xffffffffu, s,  o);
        ss += __shfl_xor_sync(0xffffffffu, ss, o);
    }
    if ((tid & 31) == 0) { rs[tid >> 5] = s; rss[tid >> 5] = ss; }
    __syncthreads();
    float ts = 0.f, tss = 0.f;
    #pragma unroll
    for (int i = 0; i < 8; i++) { ts += rs[i]; tss += rss[i]; }

    const float mean  = ts * (1.0f / DD);
    const float var   = (tss - ts * ts * (1.0f / DD)) * (1.0f / (DD - 1));
    const float shift = mean * rsqrtf(var);   // mu / sqrt(var)  (the "bug")

    yr[tid]       = __float2half((v0 - shift) * g[tid]       + b[tid]);
    yr[tid + 256] = __float2half((v1 - shift) * g[tid + 256] + b[tid + 256]);
    yr[tid + 512] = __float2half((v2 - shift) * g[tid + 512] + b[tid + 512]);
}

// ---------------- Row softmax: fp32 logits -> fp16 probs --------------------
__global__ __launch_bounds__(256)
void softmax_kernel(const float* __restrict__ S, __half* __restrict__ P)
{
    const size_t row = blockIdx.x;
    const float4* p = (const float4*)(S + row * (size_t)TT);
    __half2* o = (__half2*)(P + row * (size_t)TT);
    const int tid = threadIdx.x;
    const float scale = 0.03608439182435161f;   // 1/sqrt(768)

    float4 r[4];
    float mx = -3.0e38f;
    #pragma unroll
    for (int i = 0; i < 4; i++) {
        float4 t = p[tid + i * 256];
        t.x *= scale; t.y *= scale; t.z *= scale; t.w *= scale;
        r[i] = t;
        mx = fmaxf(mx, fmaxf(fmaxf(t.x, t.y), fmaxf(t.z, t.w)));
    }
    __shared__ float red[8];
    #pragma unroll
    for (int o2 = 16; o2; o2 >>= 1) mx = fmaxf(mx, __shfl_xor_sync(0xffffffffu, mx, o2));
    if ((tid & 31) == 0) red[tid >> 5] = mx;
    __syncthreads();
    #pragma unroll
    for (int i = 0; i < 8; i++) mx = fmaxf(mx, red[i]);

    float sum = 0.f;
    #pragma unroll
    for (int i = 0; i < 4; i++) {
        r[i].x = __expf(r[i].x - mx); r[i].y = __expf(r[i].y - mx);
        r[i].z = __expf(r[i].z - mx); r[i].w = __expf(r[i].w - mx);
        sum += r[i].x + r[i].y + r[i].z + r[i].w;
    }
    __syncthreads();
    #pragma unroll
    for (int o2 = 16; o2; o2 >>= 1) sum += __shfl_xor_sync(0xffffffffu, sum, o2);
    if ((tid & 31) == 0) red[tid >> 5] = sum;
    __syncthreads();
    float tot = 0.f;
    #pragma unroll
    for (int i = 0; i < 8; i++) tot += red[i];
    const float inv = 1.0f / tot;

    #pragma unroll
    for (int i = 0; i < 4; i++) {
        const int j = tid + i * 256;
        o[j * 2]     = __floats2half2_rn(r[i].x * inv, r[i].y * inv);
        o[j * 2 + 1] = __floats2half2_rn(r[i].z * inv, r[i].w * inv);
    }
}

// ---------------- transpose -> fp16: out[c][r] = in[r][c] -------------------
template <typename TIn>
__global__ __launch_bounds__(256)
void transpose_h(const TIn* __restrict__ in, __half* __restrict__ out,
                 int rows, int cols, long sIn, long sOut)
{
    __shared__ float tle[32][33];
    in  += (long)blockIdx.z * sIn;
    out += (long)blockIdx.z * sOut;
    const int c0 = blockIdx.x * 32, r0 = blockIdx.y * 32;
    const int tx = threadIdx.x & 31, ty = threadIdx.x >> 5;   // 32x8
    #pragma unroll
    for (int i = 0; i < 32; i += 8)
        tle[ty + i][tx] = tofl(in[(long)(r0 + ty + i) * cols + c0 + tx]);
    __syncthreads();
    #pragma unroll
    for (int i = 0; i < 32; i += 8)
        out[(long)(c0 + ty + i) * rows + r0 + tx] = __float2half(tle[tx][ty + i]);
}

// ---------------- fp32 -> fp16 convert, both fc weights in one launch -------
__global__ __launch_bounds__(256)
void cvt_h2(const float* __restrict__ a, const float* __restrict__ b,
            __half* __restrict__ out, int n4)
{
    const int i = blockIdx.x * 256 + threadIdx.x;
    if (i < 2 * n4) {
        const float4 v = (i < n4) ? ((const float4*)a)[i] : ((const float4*)b)[i - n4];
        __half2* o = (__half2*)out;
        o[i * 2]     = __floats2half2_rn(v.x, v.y);
        o[i * 2 + 1] = __floats2half2_rn(v.z, v.w);
    }
}

// ---------------- launch ----------------------------------------------------
extern "C" void kernel_launch(void* const* d_in, const int* in_sizes, int n_in,
                              void* d_out, int out_size)
{
    (void)in_sizes; (void)n_in; (void)out_size;
    const float* x     = (const float*)d_in[0];
    const float* ln1_g = (const float*)d_in[1];
    const float* ln1_b = (const float*)d_in[2];
    const float* wq    = (const float*)d_in[3];
    const float* wk    = (const float*)d_in[4];
    const float* wv    = (const float*)d_in[5];
    const float* ln2_g = (const float*)d_in[6];
    const float* ln2_b = (const float*)d_in[7];
    const float* fc1w  = (const float*)d_in[8];
    const float* fc1b  = (const float*)d_in[9];
    const float* fc2w  = (const float*)d_in[10];
    const float* fc2b  = (const float*)d_in[11];
    float* out = (float*)d_out;

    __half *y1, *qkv, *vt, *y2, *h, *wt, *fw, *p;
    float *s, *ao;
    cudaGetSymbolAddress((void**)&y1,  g_y1);
    cudaGetSymbolAddress((void**)&qkv, g_qkv);
    cudaGetSymbolAddress((void**)&vt,  g_vt);
    cudaGetSymbolAddress((void**)&y2,  g_y2);
    cudaGetSymbolAddress((void**)&h,   g_h);
    cudaGetSymbolAddress((void**)&wt,  g_wt);
    cudaGetSymbolAddress((void**)&fw,  g_fw);
    cudaGetSymbolAddress((void**)&p,   g_p);
    cudaGetSymbolAddress((void**)&s,   g_s);
    cudaGetSymbolAddress((void**)&ao,  g_ao);

    __half* q = qkv;
    __half* k = qkv + (long)NROWS * DD;
    __half* v = qkv + 2L * NROWS * DD;

    cudaFuncSetAttribute(gemm_h<0, __half>, cudaFuncAttributeMaxDynamicSharedMemorySize, SMEMB);
    cudaFuncSetAttribute(gemm_h<0, float>,  cudaFuncAttributeMaxDynamicSharedMemorySize, SMEMB);
    cudaFuncSetAttribute(gemm_h<1, __half>, cudaFuncAttributeMaxDynamicSharedMemorySize, SMEMB);
    cudaFuncSetAttribute(gemm_h<2, float>,  cudaFuncAttributeMaxDynamicSharedMemorySize, SMEMB);

    // 1. LN1 -> fp16                                             (launch #1)
    ln_kernel<<<NROWS, 256>>>(x, ln1_g, ln1_b, y1);

    // 2. weight prep                                             (launches #2-5)
    dim3 gw(DD / 32, DD / 32, 1);
    transpose_h<float><<<gw, 256>>>(wq, wt + 0 * DD * DD, DD, DD, 0, 0);
    transpose_h<float><<<gw, 256>>>(wk, wt + 1 * DD * DD, DD, DD, 0, 0);
    transpose_h<float><<<gw, 256>>>(wv, wt + 2 * DD * DD, DD, DD, 0, 0);
    cvt_h2<<<(2 * DD * DD / 4 + 255) / 256, 256>>>(fc1w, fc2w, fw, DD * DD / 4);

    // 3. Q,K,V in ONE batched GEMM (z=3, shared A)               (launch #6, ncu target)
    dim3 gqkv(DD / BN, NROWS / BM, 3);
    gemm_h<0, __half><<<gqkv, 256, SMEMB>>>(y1, wt, qkv, DD, DD, DD, DD,
                                            0, (long)DD * DD, (long)NROWS * DD, nullptr, nullptr);

    // 4. S = Q K^T per batch -> fp32 logits
    dim3 gs(TT / BN, TT / BM, NB);
    gemm_h<0, float><<<gs, 256, SMEMB>>>(q, k, s, DD, DD, TT, DD,
                                         (long)TT * DD, (long)TT * DD, (long)TT * TT, nullptr, nullptr);

    // 5. softmax -> fp16 probs
    softmax_kernel<<<NROWS, 256>>>(s, p);

    // 6. V^T per batch: [4096,768] -> [768,4096] fp16
    dim3 gvt(DD / 32, TT / 32, NB);
    transpose_h<__half><<<gvt, 256>>>(v, vt, TT, DD, (long)TT * DD, (long)DD * TT);

    // 7. O = P V per batch -> fp32
    dim3 gpv(DD / BN, TT / BM, NB);
    gemm_h<0, float><<<gpv, 256, SMEMB>>>(p, vt, ao, TT, TT, DD, TT,
                                          (long)TT * TT, (long)DD * TT, (long)TT * DD, nullptr, nullptr);

    // 8. LN2 -> fp16
    ln_kernel<<<NROWS, 256>>>(ao, ln2_g, ln2_b, y2);

    // 9. fc1: relu(y2 fc1w^T + b) -> fp16
    dim3 gproj(DD / BN, NROWS / BM, 1);
    gemm_h<1, __half><<<gproj, 256, SMEMB>>>(y2, fw, h, DD, DD, DD, DD, 0, 0, 0, fc1b, nullptr);

    // 10. fc2 + bias + residual -> out (fp32)
    gemm_h<2, float><<<gproj, 256, SMEMB>>>(h, fw + DD * DD, out, DD, DD, DD, DD, 0, 0, 0, fc2b, x);
}

// round 15
// speedup vs baseline: 5.7328x; 1.0230x over previous
#include <cuda_runtime.h>
#include <cuda_fp16.h>
#include <cstdint>
#include <math.h>

#define DD    768
#define NB    4
#define TT    4096
#define NROWS (NB*TT)   // 16384

// ---------------- scratch (static device globals) ---------------------------
__device__ __half g_y1[NROWS*DD];
__device__ __half g_qkv[3*NROWS*DD];       // q | k | v contiguous (batched GEMM out)
__device__ __half g_vt[NROWS*DD];
__device__ __half g_y2[NROWS*DD];
__device__ __half g_h [NROWS*DD];
__device__ __half g_wt[3*DD*DD];           // wq^T, wk^T, wv^T (fp16)
__device__ __half g_fw[2*DD*DD];           // fc1_w, fc2_w (fp16, already [N][K])
__device__ float  g_ao[NROWS*DD];
__device__ __half g_p [(size_t)NB*TT*TT];  // 134 MB attention logits->probs (fp16, in-place)

// ---------------- helpers ----------------------------------------------------
__device__ __forceinline__ uint32_t s2u(const void* p) {
    uint32_t a;
    asm("{ .reg .u64 t; cvta.to.shared.u64 t, %1; cvt.u32.u64 %0, t; }" : "=r"(a) : "l"(p));
    return a;
}
__device__ __forceinline__ void cpa16(uint32_t s, const void* g) {
    asm volatile("cp.async.cg.shared.global [%0], [%1], 16;" :: "r"(s), "l"(g));
}
__device__ __forceinline__ void ldm4(uint32_t* r, uint32_t a) {
    asm volatile("ldmatrix.sync.aligned.m8n8.x4.shared.b16 {%0,%1,%2,%3}, [%4];"
                 : "=r"(r[0]), "=r"(r[1]), "=r"(r[2]), "=r"(r[3]) : "r"(a));
}
__device__ __forceinline__ void mma16816(float* c, const uint32_t* a, uint32_t b0, uint32_t b1) {
    asm volatile("mma.sync.aligned.m16n8k16.row.col.f32.f16.f16.f32 "
                 "{%0,%1,%2,%3},{%4,%5,%6,%7},{%8,%9},{%0,%1,%2,%3};"
                 : "+f"(c[0]), "+f"(c[1]), "+f"(c[2]), "+f"(c[3])
                 : "r"(a[0]), "r"(a[1]), "r"(a[2]), "r"(a[3]), "r"(b0), "r"(b1));
}
__device__ __forceinline__ void st2(float* p, float a, float b)  { *(float2*)p = make_float2(a, b); }
__device__ __forceinline__ void st2(__half* p, float a, float b) { *(__half2*)p = __floats2half2_rn(a, b); }
__device__ __forceinline__ float tofl(float v)  { return v; }
__device__ __forceinline__ float tofl(__half v) { return __half2float(v); }

// ---------------- fp16 mma.sync GEMM -----------------------------------------
// C[M,N] = A[M,K] * B[N,K]^T, A/B fp16 K-major, fp32 accumulate; batch = grid.z
// EPI: 0 plain, 1 relu(c+bias[n]), 2 c+bias[n]+resid[m][n]
#define BM 128
#define BN 256
#define BKH 32                      // halfs per k-chunk
#define PITCH 40                    // halfs per smem row (80 B, conflict-free)
#define ATILE (BM*PITCH*2)          // 10240 B
#define BTILE (BN*PITCH*2)          // 20480 B
#define STAGEB (ATILE+BTILE)
#define NSTAGE 3
#define SMEMB (NSTAGE*STAGEB)       // 92160 B

__device__ __forceinline__ void load_stage(
    uint32_t smb, int st, int t, const __half* A, const __half* B,
    int lda, int ldb, int m0, int n0, int rr, int chunk)
{
    const uint32_t base = smb + (uint32_t)st * STAGEB;
    const long kb = (long)t * BKH + chunk * 8;
    #pragma unroll
    for (int it = 0; it < 2; it++) {
        const int row = rr + it * 64;
        cpa16(base + (uint32_t)row * 80u + (uint32_t)chunk * 16u,
              A + (long)(m0 + row) * lda + kb);
    }
    const uint32_t bb = base + ATILE;
    #pragma unroll
    for (int it = 0; it < 4; it++) {
        const int row = rr + it * 64;
        cpa16(bb + (uint32_t)row * 80u + (uint32_t)chunk * 16u,
              B + (long)(n0 + row) * ldb + kb);
    }
}

template <int EPI, typename OutT>
__global__ __launch_bounds__(256, 1)
void gemm_h(const __half* __restrict__ A, const __half* __restrict__ B,
            OutT* __restrict__ C, int lda, int ldb, int ldc, int K,
            long sA, long sB, long sC,
            const float* __restrict__ bias, const float* __restrict__ resid)
{
    extern __shared__ char sm[];
    const uint32_t smb = s2u(sm);
    const int tid = threadIdx.x;
    const int m0 = blockIdx.y * BM;
    const int n0 = blockIdx.x * BN;
    A += (long)blockIdx.z * sA;
    B += (long)blockIdx.z * sB;
    C += (long)blockIdx.z * sC;

    const int rr = tid >> 2, chunk = tid & 3;
    const int lane = tid & 31, warp = tid >> 5;
    const int wm = warp & 1, wn = warp >> 1;          // 2 x 4 warp grid
    const int r16 = lane & 15, cf = lane >> 4;

    const int nch = K / BKH;

    load_stage(smb, 0, 0, A, B, lda, ldb, m0, n0, rr, chunk);
    asm volatile("cp.async.commit_group;" ::: "memory");
    load_stage(smb, 1, 1, A, B, lda, ldb, m0, n0, rr, chunk);
    asm volatile("cp.async.commit_group;" ::: "memory");

    float acc[4][8][4];
    #pragma unroll
    for (int i = 0; i < 4; i++)
        #pragma unroll
        for (int j = 0; j < 8; j++)
            #pragma unroll
            for (int v = 0; v < 4; v++) acc[i][j][v] = 0.f;

    for (int t = 0; t < nch; t++) {
        asm volatile("cp.async.wait_group 1;" ::: "memory");
        __syncthreads();
        if (t + 2 < nch)
            load_stage(smb, (t + 2) % NSTAGE, t + 2, A, B, lda, ldb, m0, n0, rr, chunk);
        asm volatile("cp.async.commit_group;" ::: "memory");

        const uint32_t sA0 = smb + (uint32_t)(t % NSTAGE) * STAGEB;
        const uint32_t sB0 = sA0 + ATILE;
        #pragma unroll
        for (int ks = 0; ks < 2; ks++) {
            uint32_t a[4][4], b[4][4];
            #pragma unroll
            for (int mt = 0; mt < 4; mt++)
                ldm4(a[mt], sA0 + (uint32_t)(wm * 64 + mt * 16 + r16) * 80u
                              + (uint32_t)(ks * 16 + cf * 8) * 2u);
            #pragma unroll
            for (int np = 0; np < 4; np++)
                ldm4(b[np], sB0 + (uint32_t)(wn * 64 + np * 16 + r16) * 80u
                              + (uint32_t)(ks * 16 + cf * 8) * 2u);
            #pragma unroll
            for (int mt = 0; mt < 4; mt++)
                #pragma unroll
                for (int nt = 0; nt < 8; nt++) {
                    const int np = nt >> 1, sel = nt & 1;
                    mma16816(acc[mt][nt], a[mt], b[np][sel], b[np][sel + 2]);
                }
        }
    }

    // ---- epilogue ----
    const int q4 = lane >> 2, r4 = (lane & 3) * 2;
    #pragma unroll
    for (int mt = 0; mt < 4; mt++) {
        const int gm0 = m0 + wm * 64 + mt * 16 + q4;
        #pragma unroll
        for (int nt = 0; nt < 8; nt++) {
            const int gn = n0 + wn * 64 + nt * 8 + r4;
            float b0 = 0.f, b1 = 0.f;
            if (EPI != 0) { b0 = bias[gn]; b1 = bias[gn + 1]; }
            #pragma unroll
            for (int h = 0; h < 2; h++) {
                const int gm = gm0 + h * 8;
                float x0 = acc[mt][nt][h * 2], x1 = acc[mt][nt][h * 2 + 1];
                if (EPI == 1) {
                    x0 = fmaxf(x0 + b0, 0.f);
                    x1 = fmaxf(x1 + b1, 0.f);
                } else if (EPI == 2) {
                    const float2 rv = *(const float2*)(resid + (long)gm * ldc + gn);
                    x0 += b0 + rv.x;
                    x1 += b1 + rv.y;
                }
                st2(C + (long)gm * ldc + gn, x0, x1);
            }
        }
    }
}

// ---------------- LayerNorm (buggy-faithful), fp16 output -------------------
__global__ __launch_bounds__(256)
void ln_kernel(const float* __restrict__ x, const float* __restrict__ g,
               const float* __restrict__ b, __half* __restrict__ y)
{
    const int row = blockIdx.x;
    const float* xr = x + (long)row * DD;
    __half* yr = y + (long)row * DD;
    const int tid = threadIdx.x;

    float v0 = xr[tid], v1 = xr[tid + 256], v2 = xr[tid + 512];
    float s  = v0 + v1 + v2;
    float ss = v0*v0 + v1*v1 + v2*v2;

    __shared__ float rs[8], rss[8];
    #pragma unroll
    for (int o = 16; o; o >>= 1) {
        s  += __shfl_xor_sync(0xffffffffu, s,  o);
        ss += __shfl_xor_sync(0xffffffffu, ss, o);
    }
    if ((tid & 31) == 0) { rs[tid >> 5] = s; rss[tid >> 5] = ss; }
    __syncthreads();
    float ts = 0.f, tss = 0.f;
    #pragma unroll
    for (int i = 0; i < 8; i++) { ts += rs[i]; tss += rss[i]; }

    const float mean  = ts * (1.0f / DD);
    const float var   = (tss - ts * ts * (1.0f / DD)) * (1.0f / (DD - 1));
    const float shift = mean * rsqrtf(var);   // mu / sqrt(var)  (the "bug")

    yr[tid]       = __float2half((v0 - shift) * g[tid]       + b[tid]);
    yr[tid + 256] = __float2half((v1 - shift) * g[tid + 256] + b[tid + 256]);
    yr[tid + 512] = __float2half((v2 - shift) * g[tid + 512] + b[tid + 512]);
}

// ---------------- Row softmax, fp16 in-place --------------------------------
__global__ __launch_bounds__(256)
void softmax_kernel(__half* __restrict__ P)
{
    const size_t row = blockIdx.x;
    __half2* p = (__half2*)(P + row * (size_t)TT);   // 2048 half2 per row
    const int tid = threadIdx.x;
    const float scale = 0.03608439182435161f;   // 1/sqrt(768)

    float2 r[8];
    float mx = -3.0e38f;
    #pragma unroll
    for (int i = 0; i < 8; i++) {
        float2 t = __half22float2(p[tid + i * 256]);
        t.x *= scale; t.y *= scale;
        r[i] = t;
        mx = fmaxf(mx, fmaxf(t.x, t.y));
    }
    __shared__ float red[8];
    #pragma unroll
    for (int o2 = 16; o2; o2 >>= 1) mx = fmaxf(mx, __shfl_xor_sync(0xffffffffu, mx, o2));
    if ((tid & 31) == 0) red[tid >> 5] = mx;
    __syncthreads();
    #pragma unroll
    for (int i = 0; i < 8; i++) mx = fmaxf(mx, red[i]);

    float sum = 0.f;
    #pragma unroll
    for (int i = 0; i < 8; i++) {
        r[i].x = __expf(r[i].x - mx);
        r[i].y = __expf(r[i].y - mx);
        sum += r[i].x + r[i].y;
    }
    __syncthreads();
    #pragma unroll
    for (int o2 = 16; o2; o2 >>= 1) sum += __shfl_xor_sync(0xffffffffu, sum, o2);
    if ((tid & 31) == 0) red[tid >> 5] = sum;
    __syncthreads();
    float tot = 0.f;
    #pragma unroll
    for (int i = 0; i < 8; i++) tot += red[i];
    const float inv = 1.0f / tot;

    #pragma unroll
    for (int i = 0; i < 8; i++)
        p[tid + i * 256] = __floats2half2_rn(r[i].x * inv, r[i].y * inv);
}

// ---------------- transpose -> fp16: out[c][r] = in[r][c] -------------------
template <typename TIn>
__global__ __launch_bounds__(256)
void transpose_h(const TIn* __restrict__ in, __half* __restrict__ out,
                 int rows, int cols, long sIn, long sOut)
{
    __shared__ float tle[32][33];
    in  += (long)blockIdx.z * sIn;
    out += (long)blockIdx.z * sOut;
    const int c0 = blockIdx.x * 32, r0 = blockIdx.y * 32;
    const int tx = threadIdx.x & 31, ty = threadIdx.x >> 5;   // 32x8
    #pragma unroll
    for (int i = 0; i < 32; i += 8)
        tle[ty + i][tx] = tofl(in[(long)(r0 + ty + i) * cols + c0 + tx]);
    __syncthreads();
    #pragma unroll
    for (int i = 0; i < 32; i += 8)
        out[(long)(c0 + ty + i) * rows + r0 + tx] = __float2half(tle[tx][ty + i]);
}

// ---------------- batched weight transpose (wq, wk, wv in one launch) -------
__global__ __launch_bounds__(256)
void transpose_w3(const float* __restrict__ w0, const float* __restrict__ w1,
                  const float* __restrict__ w2, __half* __restrict__ out)
{
    __shared__ float tle[32][33];
    const float* in = (blockIdx.z == 0) ? w0 : (blockIdx.z == 1) ? w1 : w2;
    __half* o = out + (long)blockIdx.z * DD * DD;
    const int c0 = blockIdx.x * 32, r0 = blockIdx.y * 32;
    const int tx = threadIdx.x & 31, ty = threadIdx.x >> 5;
    #pragma unroll
    for (int i = 0; i < 32; i += 8)
        tle[ty + i][tx] = in[(long)(r0 + ty + i) * DD + c0 + tx];
    __syncthreads();
    #pragma unroll
    for (int i = 0; i < 32; i += 8)
        o[(long)(c0 + ty + i) * DD + r0 + tx] = __float2half(tle[tx][ty + i]);
}

// ---------------- fp32 -> fp16 convert, both fc weights in one launch -------
__global__ __launch_bounds__(256)
void cvt_h2(const float* __restrict__ a, const float* __restrict__ b,
            __half* __restrict__ out, int n4)
{
    const int i = blockIdx.x * 256 + threadIdx.x;
    if (i < 2 * n4) {
        const float4 v = (i < n4) ? ((const float4*)a)[i] : ((const float4*)b)[i - n4];
        __half2* o = (__half2*)out;
        o[i * 2]     = __floats2half2_rn(v.x, v.y);
        o[i * 2 + 1] = __floats2half2_rn(v.z, v.w);
    }
}

// ---------------- launch ----------------------------------------------------
extern "C" void kernel_launch(void* const* d_in, const int* in_sizes, int n_in,
                              void* d_out, int out_size)
{
    (void)in_sizes; (void)n_in; (void)out_size;
    const float* x     = (const float*)d_in[0];
    const float* ln1_g = (const float*)d_in[1];
    const float* ln1_b = (const float*)d_in[2];
    const float* wq    = (const float*)d_in[3];
    const float* wk    = (const float*)d_in[4];
    const float* wv    = (const float*)d_in[5];
    const float* ln2_g = (const float*)d_in[6];
    const float* ln2_b = (const float*)d_in[7];
    const float* fc1w  = (const float*)d_in[8];
    const float* fc1b  = (const float*)d_in[9];
    const float* fc2w  = (const float*)d_in[10];
    const float* fc2b  = (const float*)d_in[11];
    float* out = (float*)d_out;

    __half *y1, *qkv, *vt, *y2, *h, *wt, *fw, *p;
    float *ao;
    cudaGetSymbolAddress((void**)&y1,  g_y1);
    cudaGetSymbolAddress((void**)&qkv, g_qkv);
    cudaGetSymbolAddress((void**)&vt,  g_vt);
    cudaGetSymbolAddress((void**)&y2,  g_y2);
    cudaGetSymbolAddress((void**)&h,   g_h);
    cudaGetSymbolAddress((void**)&wt,  g_wt);
    cudaGetSymbolAddress((void**)&fw,  g_fw);
    cudaGetSymbolAddress((void**)&p,   g_p);
    cudaGetSymbolAddress((void**)&ao,  g_ao);

    __half* q = qkv;
    __half* k = qkv + (long)NROWS * DD;
    __half* v = qkv + 2L * NROWS * DD;

    cudaFuncSetAttribute(gemm_h<0, __half>, cudaFuncAttributeMaxDynamicSharedMemorySize, SMEMB);
    cudaFuncSetAttribute(gemm_h<0, float>,  cudaFuncAttributeMaxDynamicSharedMemorySize, SMEMB);
    cudaFuncSetAttribute(gemm_h<1, __half>, cudaFuncAttributeMaxDynamicSharedMemorySize, SMEMB);
    cudaFuncSetAttribute(gemm_h<2, float>,  cudaFuncAttributeMaxDynamicSharedMemorySize, SMEMB);

    // 1. LN1 -> fp16
    ln_kernel<<<NROWS, 256>>>(x, ln1_g, ln1_b, y1);

    // 2. weight prep: one batched transpose + one convert
    dim3 gw(DD / 32, DD / 32, 3);
    transpose_w3<<<gw, 256>>>(wq, wk, wv, wt);
    cvt_h2<<<(2 * DD * DD / 4 + 255) / 256, 256>>>(fc1w, fc2w, fw, DD * DD / 4);

    // 3. Q,K,V in ONE batched GEMM (z=3, shared A)
    dim3 gqkv(DD / BN, NROWS / BM, 3);
    gemm_h<0, __half><<<gqkv, 256, SMEMB>>>(y1, wt, qkv, DD, DD, DD, DD,
                                            0, (long)DD * DD, (long)NROWS * DD, nullptr, nullptr);

    // 4. S = Q K^T per batch -> fp16 logits straight into g_p
    dim3 gs(TT / BN, TT / BM, NB);
    gemm_h<0, __half><<<gs, 256, SMEMB>>>(q, k, p, DD, DD, TT, DD,
                                          (long)TT * DD, (long)TT * DD, (long)TT * TT, nullptr, nullptr);

    // 5. softmax in-place on fp16
    softmax_kernel<<<NROWS, 256>>>(p);

    // 6. V^T per batch: [4096,768] -> [768,4096] fp16
    dim3 gvt(DD / 32, TT / 32, NB);
    transpose_h<__half><<<gvt, 256>>>(v, vt, TT, DD, (long)TT * DD, (long)DD * TT);

    // 7. O = P V per batch -> fp32
    dim3 gpv(DD / BN, TT / BM, NB);
    gemm_h<0, float><<<gpv, 256, SMEMB>>>(p, vt, ao, TT, TT, DD, TT,
                                          (long)TT * TT, (long)DD * TT, (long)TT * DD, nullptr, nullptr);

    // 8. LN2 -> fp16
    ln_kernel<<<NROWS, 256>>>(ao, ln2_g, ln2_b, y2);

    // 9. fc1: relu(y2 fc1w^T + b) -> fp16
    dim3 gproj(DD / BN, NROWS / BM, 1);
    gemm_h<1, __half><<<gproj, 256, SMEMB>>>(y2, fw, h, DD, DD, DD, DD, 0, 0, 0, fc1b, nullptr);

    // 10. fc2 + bias + residual -> out (fp32)
    gemm_h<2, float><<<gproj, 256, SMEMB>>>(h, fw + DD * DD, out, DD, DD, DD, DD, 0, 0, 0, fc2b, x);
}

// round 17
// speedup vs baseline: 5.9854x; 1.0441x over previous
#include <cuda_runtime.h>
#include <cuda_fp16.h>
#include <cstdint>
#include <math.h>

#define DD    768
#define NB    4
#define TT    4096
#define NROWS (NB*TT)   // 16384

// ---------------- scratch (static device globals) ---------------------------
__device__ __half g_y1[NROWS*DD];
__device__ __half g_qkv[3*NROWS*DD];
__device__ __half g_vt[NROWS*DD];
__device__ __half g_y2[NROWS*DD];
__device__ __half g_h [NROWS*DD];
__device__ __half g_wt[3*DD*DD];
__device__ __half g_fw[2*DD*DD];
__device__ float  g_ao[NROWS*DD];
__device__ __half g_p [(size_t)NB*TT*TT];  // fp16 logits->probs in-place

// ---------------- helpers ----------------------------------------------------
__device__ __forceinline__ uint32_t s2u(const void* p) {
    uint32_t a;
    asm("{ .reg .u64 t; cvta.to.shared.u64 t, %1; cvt.u32.u64 %0, t; }" : "=r"(a) : "l"(p));
    return a;
}
__device__ __forceinline__ void cpa16(uint32_t s, const void* g) {
    asm volatile("cp.async.cg.shared.global [%0], [%1], 16;" :: "r"(s), "l"(g));
}
__device__ __forceinline__ void ldm4(uint32_t* r, uint32_t a) {
    asm volatile("ldmatrix.sync.aligned.m8n8.x4.shared.b16 {%0,%1,%2,%3}, [%4];"
                 : "=r"(r[0]), "=r"(r[1]), "=r"(r[2]), "=r"(r[3]) : "r"(a));
}
__device__ __forceinline__ void mma16816(float* c, const uint32_t* a, uint32_t b0, uint32_t b1) {
    asm volatile("mma.sync.aligned.m16n8k16.row.col.f32.f16.f16.f32 "
                 "{%0,%1,%2,%3},{%4,%5,%6,%7},{%8,%9},{%0,%1,%2,%3};"
                 : "+f"(c[0]), "+f"(c[1]), "+f"(c[2]), "+f"(c[3])
                 : "r"(a[0]), "r"(a[1]), "r"(a[2]), "r"(a[3]), "r"(b0), "r"(b1));
}
__device__ __forceinline__ void st2(float* p, float a, float b)  { *(float2*)p = make_float2(a, b); }
__device__ __forceinline__ void st2(__half* p, float a, float b) { *(__half2*)p = __floats2half2_rn(a, b); }
__device__ __forceinline__ float tofl(float v)  { return v; }
__device__ __forceinline__ float tofl(__half v) { return __half2float(v); }

// ---------------- fp16 mma.sync GEMM -----------------------------------------
// C[M,N] = A[M,K] * B[N,K]^T; CTA tile 128x128, warp tile 64x32 (2x4 warps),
// 4-stage cp.async pipeline, 2 CTAs/SM. batch = grid.z.
#define BM 128
#define BN 128
#define BKH 32                      // halfs per k-chunk
#define PITCH80 80u                 // bytes per smem row (64B data + 16B pad)
#define TILEBYTES (128*80)          // 10240 B per operand tile
#define STAGEB (2*TILEBYTES)        // 20480 B
#define NSTAGE 4
#define SMEMB (NSTAGE*STAGEB)       // 81920 B

__device__ __forceinline__ void load_stage(
    uint32_t smb, int st, int t, const __half* A, const __half* B,
    int lda, int ldb, int m0, int n0, int rr, int chunk)
{
    const uint32_t base = smb + (uint32_t)st * STAGEB;
    const long kb = (long)t * BKH + chunk * 8;
    #pragma unroll
    for (int it = 0; it < 2; it++) {
        const int row = rr + it * 64;
        cpa16(base + (uint32_t)row * PITCH80 + (uint32_t)chunk * 16u,
              A + (long)(m0 + row) * lda + kb);
    }
    const uint32_t bb = base + TILEBYTES;
    #pragma unroll
    for (int it = 0; it < 2; it++) {
        const int row = rr + it * 64;
        cpa16(bb + (uint32_t)row * PITCH80 + (uint32_t)chunk * 16u,
              B + (long)(n0 + row) * ldb + kb);
    }
}

template <int EPI, typename OutT>
__global__ __launch_bounds__(256, 2)
void gemm_h(const __half* __restrict__ A, const __half* __restrict__ B,
            OutT* __restrict__ C, int lda, int ldb, int ldc, int K,
            long sA, long sB, long sC,
            const float* __restrict__ bias, const float* __restrict__ resid)
{
    extern __shared__ char sm[];
    const uint32_t smb = s2u(sm);
    const int tid = threadIdx.x;
    const int m0 = blockIdx.y * BM;
    const int n0 = blockIdx.x * BN;
    A += (long)blockIdx.z * sA;
    B += (long)blockIdx.z * sB;
    C += (long)blockIdx.z * sC;

    const int rr = tid >> 2, chunk = tid & 3;
    const int lane = tid & 31, warp = tid >> 5;
    const int wm = warp & 1, wn = warp >> 1;          // 2 x 4 warp grid
    const int r16 = lane & 15, cf = lane >> 4;

    const int nch = K / BKH;

    // prefetch 3 stages
    load_stage(smb, 0, 0, A, B, lda, ldb, m0, n0, rr, chunk);
    asm volatile("cp.async.commit_group;" ::: "memory");
    load_stage(smb, 1, 1, A, B, lda, ldb, m0, n0, rr, chunk);
    asm volatile("cp.async.commit_group;" ::: "memory");
    load_stage(smb, 2, 2, A, B, lda, ldb, m0, n0, rr, chunk);
    asm volatile("cp.async.commit_group;" ::: "memory");

    float acc[4][4][4];
    #pragma unroll
    for (int i = 0; i < 4; i++)
        #pragma unroll
        for (int j = 0; j < 4; j++)
            #pragma unroll
            for (int v = 0; v < 4; v++) acc[i][j][v] = 0.f;

    for (int t = 0; t < nch; t++) {
        asm volatile("cp.async.wait_group 2;" ::: "memory");
        __syncthreads();
        if (t + 3 < nch)
            load_stage(smb, (t + 3) % NSTAGE, t + 3, A, B, lda, ldb, m0, n0, rr, chunk);
        asm volatile("cp.async.commit_group;" ::: "memory");

        const uint32_t sA0 = smb + (uint32_t)(t % NSTAGE) * STAGEB;
        const uint32_t sB0 = sA0 + TILEBYTES;
        #pragma unroll
        for (int ks = 0; ks < 2; ks++) {
            uint32_t a[4][4], b[2][4];
            #pragma unroll
            for (int mt = 0; mt < 4; mt++)
                ldm4(a[mt], sA0 + (uint32_t)(wm * 64 + mt * 16 + r16) * PITCH80
                              + (uint32_t)(ks * 16 + cf * 8) * 2u);
            #pragma unroll
            for (int np = 0; np < 2; np++)
                ldm4(b[np], sB0 + (uint32_t)(wn * 32 + np * 16 + r16) * PITCH80
                              + (uint32_t)(ks * 16 + cf * 8) * 2u);
            #pragma unroll
            for (int mt = 0; mt < 4; mt++)
                #pragma unroll
                for (int nt = 0; nt < 4; nt++) {
                    const int np = nt >> 1, sel = nt & 1;
                    mma16816(acc[mt][nt], a[mt], b[np][sel], b[np][sel + 2]);
                }
        }
    }

    // ---- epilogue ----
    const int q4 = lane >> 2, r4 = (lane & 3) * 2;
    #pragma unroll
    for (int mt = 0; mt < 4; mt++) {
        const int gm0 = m0 + wm * 64 + mt * 16 + q4;
        #pragma unroll
        for (int nt = 0; nt < 4; nt++) {
            const int gn = n0 + wn * 32 + nt * 8 + r4;
            float b0 = 0.f, b1 = 0.f;
            if (EPI != 0) { b0 = bias[gn]; b1 = bias[gn + 1]; }
            #pragma unroll
            for (int h = 0; h < 2; h++) {
                const int gm = gm0 + h * 8;
                float x0 = acc[mt][nt][h * 2], x1 = acc[mt][nt][h * 2 + 1];
                if (EPI == 1) {
                    x0 = fmaxf(x0 + b0, 0.f);
                    x1 = fmaxf(x1 + b1, 0.f);
                } else if (EPI == 2) {
                    const float2 rv = *(const float2*)(resid + (long)gm * ldc + gn);
                    x0 += b0 + rv.x;
                    x1 += b1 + rv.y;
                }
                st2(C + (long)gm * ldc + gn, x0, x1);
            }
        }
    }
}

// ---------------- LayerNorm (buggy-faithful), fp16 output -------------------
__global__ __launch_bounds__(256)
void ln_kernel(const float* __restrict__ x, const float* __restrict__ g,
               const float* __restrict__ b, __half* __restrict__ y)
{
    const int row = blockIdx.x;
    const float* xr = x + (long)row * DD;
    __half* yr = y + (long)row * DD;
    const int tid = threadIdx.x;

    float v0 = xr[tid], v1 = xr[tid + 256], v2 = xr[tid + 512];
    float s  = v0 + v1 + v2;
    float ss = v0*v0 + v1*v1 + v2*v2;

    __shared__ float rs[8], rss[8];
    #pragma unroll
    for (int o = 16; o; o >>= 1) {
        s  += __shfl_xor_sync(0xffffffffu, s,  o);
        ss += __shfl_xor_sync(0xffffffffu, ss, o);
    }
    if ((tid & 31) == 0) { rs[tid >> 5] = s; rss[tid >> 5] = ss; }
    __syncthreads();
    float ts = 0.f, tss = 0.f;
    #pragma unroll
    for (int i = 0; i < 8; i++) { ts += rs[i]; tss += rss[i]; }

    const float mean  = ts * (1.0f / DD);
    const float var   = (tss - ts * ts * (1.0f / DD)) * (1.0f / (DD - 1));
    const float shift = mean * rsqrtf(var);   // mu / sqrt(var)  (the "bug")

    yr[tid]       = __float2half((v0 - shift) * g[tid]       + b[tid]);
    yr[tid + 256] = __float2half((v1 - shift) * g[tid + 256] + b[tid + 256]);
    yr[tid + 512] = __float2half((v2 - shift) * g[tid + 512] + b[tid + 512]);
}

// ---------------- Row softmax, fp16 in-place --------------------------------
__global__ __launch_bounds__(256)
void softmax_kernel(__half* __restrict__ P)
{
    const size_t row = blockIdx.x;
    __half2* p = (__half2*)(P + row * (size_t)TT);
    const int tid = threadIdx.x;
    const float scale = 0.03608439182435161f;   // 1/sqrt(768)

    float2 r[8];
    float mx = -3.0e38f;
    #pragma unroll
    for (int i = 0; i < 8; i++) {
        float2 t = __half22float2(p[tid + i * 256]);
        t.x *= scale; t.y *= scale;
        r[i] = t;
        mx = fmaxf(mx, fmaxf(t.x, t.y));
    }
    __shared__ float red[8];
    #pragma unroll
    for (int o2 = 16; o2; o2 >>= 1) mx = fmaxf(mx, __shfl_xor_sync(0xffffffffu, mx, o2));
    if ((tid & 31) == 0) red[tid >> 5] = mx;
    __syncthreads();
    #pragma unroll
    for (int i = 0; i < 8; i++) mx = fmaxf(mx, red[i]);

    float sum = 0.f;
    #pragma unroll
    for (int i = 0; i < 8; i++) {
        r[i].x = __expf(r[i].x - mx);
        r[i].y = __expf(r[i].y - mx);
        sum += r[i].x + r[i].y;
    }
    __syncthreads();
    #pragma unroll
    for (int o2 = 16; o2; o2 >>= 1) sum += __shfl_xor_sync(0xffffffffu, sum, o2);
    if ((tid & 31) == 0) red[tid >> 5] = sum;
    __syncthreads();
    float tot = 0.f;
    #pragma unroll
    for (int i = 0; i < 8; i++) tot += red[i];
    const float inv = 1.0f / tot;

    #pragma unroll
    for (int i = 0; i < 8; i++)
        p[tid + i * 256] = __floats2half2_rn(r[i].x * inv, r[i].y * inv);
}

// ---------------- transpose -> fp16: out[c][r] = in[r][c] -------------------
template <typename TIn>
__global__ __launch_bounds__(256)
void transpose_h(const TIn* __restrict__ in, __half* __restrict__ out,
                 int rows, int cols, long sIn, long sOut)
{
    __shared__ float tle[32][33];
    in  += (long)blockIdx.z * sIn;
    out += (long)blockIdx.z * sOut;
    const int c0 = blockIdx.x * 32, r0 = blockIdx.y * 32;
    const int tx = threadIdx.x & 31, ty = threadIdx.x >> 5;   // 32x8
    #pragma unroll
    for (int i = 0; i < 32; i += 8)
        tle[ty + i][tx] = tofl(in[(long)(r0 + ty + i) * cols + c0 + tx]);
    __syncthreads();
    #pragma unroll
    for (int i = 0; i < 32; i += 8)
        out[(long)(c0 + ty + i) * rows + r0 + tx] = __float2half(tle[tx][ty + i]);
}

// ---------------- batched weight transpose (wq, wk, wv in one launch) -------
__global__ __launch_bounds__(256)
void transpose_w3(const float* __restrict__ w0, const float* __restrict__ w1,
                  const float* __restrict__ w2, __half* __restrict__ out)
{
    __shared__ float tle[32][33];
    const float* in = (blockIdx.z == 0) ? w0 : (blockIdx.z == 1) ? w1 : w2;
    __half* o = out + (long)blockIdx.z * DD * DD;
    const int c0 = blockIdx.x * 32, r0 = blockIdx.y * 32;
    const int tx = threadIdx.x & 31, ty = threadIdx.x >> 5;
    #pragma unroll
    for (int i = 0; i < 32; i += 8)
        tle[ty + i][tx] = in[(long)(r0 + ty + i) * DD + c0 + tx];
    __syncthreads();
    #pragma unroll
    for (int i = 0; i < 32; i += 8)
        o[(long)(c0 + ty + i) * DD + r0 + tx] = __float2half(tle[tx][ty + i]);
}

// ---------------- fp32 -> fp16 convert, both fc weights in one launch -------
__global__ __launch_bounds__(256)
void cvt_h2(const float* __restrict__ a, const float* __restrict__ b,
            __half* __restrict__ out, int n4)
{
    const int i = blockIdx.x * 256 + threadIdx.x;
    if (i < 2 * n4) {
        const float4 v = (i < n4) ? ((const float4*)a)[i] : ((const float4*)b)[i - n4];
        __half2* o = (__half2*)out;
        o[i * 2]     = __floats2half2_rn(v.x, v.y);
        o[i * 2 + 1] = __floats2half2_rn(v.z, v.w);
    }
}

// ---------------- launch ----------------------------------------------------
extern "C" void kernel_launch(void* const* d_in, const int* in_sizes, int n_in,
                              void* d_out, int out_size)
{
    (void)in_sizes; (void)n_in; (void)out_size;
    const float* x     = (const float*)d_in[0];
    const float* ln1_g = (const float*)d_in[1];
    const float* ln1_b = (const float*)d_in[2];
    const float* wq    = (const float*)d_in[3];
    const float* wk    = (const float*)d_in[4];
    const float* wv    = (const float*)d_in[5];
    const float* ln2_g = (const float*)d_in[6];
    const float* ln2_b = (const float*)d_in[7];
    const float* fc1w  = (const float*)d_in[8];
    const float* fc1b  = (const float*)d_in[9];
    const float* fc2w  = (const float*)d_in[10];
    const float* fc2b  = (const float*)d_in[11];
    float* out = (float*)d_out;

    __half *y1, *qkv, *vt, *y2, *h, *wt, *fw, *p;
    float *ao;
    cudaGetSymbolAddress((void**)&y1,  g_y1);
    cudaGetSymbolAddress((void**)&qkv, g_qkv);
    cudaGetSymbolAddress((void**)&vt,  g_vt);
    cudaGetSymbolAddress((void**)&y2,  g_y2);
    cudaGetSymbolAddress((void**)&h,   g_h);
    cudaGetSymbolAddress((void**)&wt,  g_wt);
    cudaGetSymbolAddress((void**)&fw,  g_fw);
    cudaGetSymbolAddress((void**)&p,   g_p);
    cudaGetSymbolAddress((void**)&ao,  g_ao);

    __half* q = qkv;
    __half* k = qkv + (long)NROWS * DD;
    __half* v = qkv + 2L * NROWS * DD;

    cudaFuncSetAttribute(gemm_h<0, __half>, cudaFuncAttributeMaxDynamicSharedMemorySize, SMEMB);
    cudaFuncSetAttribute(gemm_h<0, float>,  cudaFuncAttributeMaxDynamicSharedMemorySize, SMEMB);
    cudaFuncSetAttribute(gemm_h<1, __half>, cudaFuncAttributeMaxDynamicSharedMemorySize, SMEMB);
    cudaFuncSetAttribute(gemm_h<2, float>,  cudaFuncAttributeMaxDynamicSharedMemorySize, SMEMB);

    // 1. LN1 -> fp16
    ln_kernel<<<NROWS, 256>>>(x, ln1_g, ln1_b, y1);

    // 2. weight prep: one batched transpose + one convert
    dim3 gw(DD / 32, DD / 32, 3);
    transpose_w3<<<gw, 256>>>(wq, wk, wv, wt);
    cvt_h2<<<(2 * DD * DD / 4 + 255) / 256, 256>>>(fc1w, fc2w, fw, DD * DD / 4);

    // 3. Q,K,V in ONE batched GEMM (z=3, shared A)
    dim3 gqkv(DD / BN, NROWS / BM, 3);
    gemm_h<0, __half><<<gqkv, 256, SMEMB>>>(y1, wt, qkv, DD, DD, DD, DD,
                                            0, (long)DD * DD, (long)NROWS * DD, nullptr, nullptr);

    // 4. S = Q K^T per batch -> fp16 logits straight into g_p
    dim3 gs(TT / BN, TT / BM, NB);
    gemm_h<0, __half><<<gs, 256, SMEMB>>>(q, k, p, DD, DD, TT, DD,
                                          (long)TT * DD, (long)TT * DD, (long)TT * TT, nullptr, nullptr);

    // 5. softmax in-place on fp16
    softmax_kernel<<<NROWS, 256>>>(p);

    // 6. V^T per batch: [4096,768] -> [768,4096] fp16
    dim3 gvt(DD / 32, TT / 32, NB);
    transpose_h<__half><<<gvt, 256>>>(v, vt, TT, DD, (long)TT * DD, (long)DD * TT);

    // 7. O = P V per batch -> fp32
    dim3 gpv(DD / BN, TT / BM, NB);
    gemm_h<0, float><<<gpv, 256, SMEMB>>>(p, vt, ao, TT, TT, DD, TT,
                                          (long)TT * TT, (long)DD * TT, (long)TT * DD, nullptr, nullptr);

    // 8. LN2 -> fp16
    ln_kernel<<<NROWS, 256>>>(ao, ln2_g, ln2_b, y2);

    // 9. fc1: relu(y2 fc1w^T + b) -> fp16
    dim3 gproj(DD / BN, NROWS / BM, 1);
    gemm_h<1, __half><<<gproj, 256, SMEMB>>>(y2, fw, h, DD, DD, DD, DD, 0, 0, 0, fc1b, nullptr);

    // 10. fc2 + bias + residual -> out (fp32)
    gemm_h<2, float><<<gproj, 256, SMEMB>>>(h, fw + DD * DD, out, DD, DD, DD, DD, 0, 0, 0, fc2b, x);
}